// round 15
// baseline (speedup 1.0000x reference)
#include <cuda_runtime.h>
#include <cuda_fp16.h>
#include <cstdint>

#define NN 100000
#define DD 64
#define EE 1600000
#define NCHUNK 8

// ---------------- scratch (no allocs allowed) ----------------
__device__ __align__(16) __half g_xh[NN * DD];   // fp16 copy of x
__device__ __align__(16) __half g_h1[NN * DD];   // fp16 layer-0 output
__device__ __align__(16) __half g_agg[NN * DD];  // fp16 aggregated neighbors
__device__ __align__(16) unsigned g_w1h[2 * 64 * 64];  // fp16 [wl|wr] per layer, [d][kw]
__device__ __align__(16) unsigned g_w2h[2 * 64 * 32];  // fp16 ws per layer
__device__ int g_deg[NN];
__device__ int g_rp[NN + 1];
__device__ __align__(16) int g_rank[EE];   // intra-bucket rank per edge
__device__ int g_csr[EE];
__device__ int g_bsum[128];

// ---------------- degree + rank over dst half, 4 edges/thread ----------------
__global__ void degree_rank_kernel(const int* __restrict__ dst, int* __restrict__ deg,
                                   int* __restrict__ rank, int E) {
    int i = blockIdx.x * blockDim.x + threadIdx.x;
    int e = i * 4;
    if (e + 3 < E) {
        int4 d = ((const int4*)dst)[i];
        int4 r;
        r.x = atomicAdd(&deg[d.x], 1);
        r.y = atomicAdd(&deg[d.y], 1);
        r.z = atomicAdd(&deg[d.z], 1);
        r.w = atomicAdd(&deg[d.w], 1);
        ((int4*)rank)[i] = r;
    } else if (e < E) {
        for (int j = e; j < E; j++) rank[j] = atomicAdd(&deg[dst[j]], 1);
    }
}

// ---------------- fp32 -> fp16 row conversion ----------------
__global__ void f2h_kernel(const float4* __restrict__ in, uint4* __restrict__ out, int n4) {
    int i = blockIdx.x * blockDim.x + threadIdx.x;
    if (i >= n4) return;
    float4 a = in[2 * i], b = in[2 * i + 1];
    __half2 h0 = __floats2half2_rn(a.x, a.y);
    __half2 h1 = __floats2half2_rn(a.z, a.w);
    __half2 h2 = __floats2half2_rn(b.x, b.y);
    __half2 h3 = __floats2half2_rn(b.z, b.w);
    uint4 o;
    o.x = *(unsigned int*)&h0; o.y = *(unsigned int*)&h1;
    o.z = *(unsigned int*)&h2; o.w = *(unsigned int*)&h3;
    out[i] = o;
}

// ---------------- weight precompute: fp32 -> fp16 packed, both layers ----------------
__global__ void wprep_kernel(const float* __restrict__ wl0, const float* __restrict__ wr0,
                             const float* __restrict__ ws0,
                             const float* __restrict__ wl1, const float* __restrict__ wr1,
                             const float* __restrict__ ws1,
                             unsigned* __restrict__ w1h, unsigned* __restrict__ w2h) {
    int i = blockIdx.x * blockDim.x + threadIdx.x;
    if (i >= 2 * 64 * 32) return;
    int L = i >> 11, r = i & 2047;
    int d = r >> 5, kw = r & 31;
    const float* wl = L ? wl1 : wl0;
    const float* wr = L ? wr1 : wr0;
    const float* ws = L ? ws1 : ws0;
    float2 vl = ((const float2*)wl)[d * 32 + kw];
    float2 vr = ((const float2*)wr)[d * 32 + kw];
    float2 vs = ((const float2*)ws)[d * 32 + kw];
    __half2 hl = __floats2half2_rn(vl.x, vl.y);
    __half2 hr = __floats2half2_rn(vr.x, vr.y);
    __half2 hs = __floats2half2_rn(vs.x, vs.y);
    w1h[L * 4096 + d * 64 + kw]      = *(unsigned int*)&hl;
    w1h[L * 4096 + d * 64 + 32 + kw] = *(unsigned int*)&hr;
    w2h[L * 2048 + d * 32 + kw]      = *(unsigned int*)&hs;
}

// ---------------- scan pass 1 (per-1024 block partials) ----------------
__global__ void scan1_kernel(const int* __restrict__ deg, int* __restrict__ rp,
                             int* __restrict__ bsum, int n) {
    __shared__ int wsum[8];
    int t = threadIdx.x;
    int base = blockIdx.x * 1024 + t * 4;
    int v[4];
#pragma unroll
    for (int j = 0; j < 4; j++) v[j] = (base + j < n) ? deg[base + j] : 0;
    int tot = v[0] + v[1] + v[2] + v[3];
    int lane = t & 31, w = t >> 5;
    int inc = tot;
#pragma unroll
    for (int d = 1; d < 32; d <<= 1) {
        int o = __shfl_up_sync(0xffffffffu, inc, d);
        if (lane >= d) inc += o;
    }
    if (lane == 31) wsum[w] = inc;
    __syncthreads();
    if (t == 0) {
        int r = 0;
#pragma unroll
        for (int i = 0; i < 8; i++) { int x = wsum[i]; wsum[i] = r; r += x; }
    }
    __syncthreads();
    int excl = wsum[w] + inc - tot;
    int r = excl;
#pragma unroll
    for (int j = 0; j < 4; j++) {
        if (base + j < n) rp[base + j] = r;
        r += v[j];
    }
    if (t == 255) bsum[blockIdx.x] = wsum[7] + inc;
}

// ---------------- scan pass 2+3 fused: add block prefixes ----------------
__global__ void scan23_kernel(int* __restrict__ rp, const int* __restrict__ bsum,
                              int nb, int n) {
    __shared__ int pref[129];
    int t = threadIdx.x;
    if (t < 32) {
        int carry = 0;
        for (int base = 0; base < nb; base += 32) {
            int v = (base + t < nb) ? bsum[base + t] : 0;
            int inc = v;
#pragma unroll
            for (int d = 1; d < 32; d <<= 1) {
                int o = __shfl_up_sync(0xffffffffu, inc, d);
                if (t >= d) inc += o;
            }
            if (base + t < nb) pref[base + t] = carry + inc - v;
            carry += __shfl_sync(0xffffffffu, inc, 31);
        }
        if (t == 0) pref[128] = carry;
    }
    __syncthreads();
    int i = blockIdx.x * blockDim.x + t;
    if (i < n) rp[i] += pref[i >> 10];
    if (blockIdx.x == 0 && t == 0) rp[n] = pref[128];
}

// ---------------- CSR placement: atomic-free streaming pass ----------------
__global__ void place_kernel(const int* __restrict__ src, const int* __restrict__ dst,
                             const int* __restrict__ rank, const int* __restrict__ rp,
                             int* __restrict__ csr, int E) {
    int i = blockIdx.x * blockDim.x + threadIdx.x;
    int e = i * 4;
    if (e + 3 < E) {
        int4 s = ((const int4*)src)[i];
        int4 d = ((const int4*)dst)[i];
        int4 r = ((const int4*)rank)[i];
        csr[rp[d.x] + r.x] = s.x;
        csr[rp[d.y] + r.y] = s.y;
        csr[rp[d.z] + r.z] = s.z;
        csr[rp[d.w] + r.w] = s.w;
    } else if (e < E) {
        for (int j = e; j < E; j++)
            csr[rp[dst[j]] + rank[j]] = src[j];
    }
}

// ---------------- CSR mean-gather: warp/node, half-warp/neighbor, fp16 rows ----------------
__device__ __forceinline__ void hacc(float4& a, uint2 v) {
    float2 f0 = __half22float2(*(__half2*)&v.x);
    float2 f1 = __half22float2(*(__half2*)&v.y);
    a.x += f0.x; a.y += f0.y; a.z += f1.x; a.w += f1.y;
}

__global__ void __launch_bounds__(256)
gather_kernel(const uint2* __restrict__ in2, const int* __restrict__ rp,
              const int* __restrict__ csr, uint2* __restrict__ agg2,
              int wid0, int wid1) {
    int wid = wid0 + ((blockIdx.x * blockDim.x + threadIdx.x) >> 5);
    if (wid >= wid1) return;
    int lane = threadIdx.x & 31;
    int half = lane >> 4;
    int fl = lane & 15;
    int start = rp[wid], end = rp[wid + 1];
    float4 acc = {0.f, 0.f, 0.f, 0.f};
    for (int base = start; base < end; base += 32) {
        int nn = min(32, end - base);
        int s = (lane < nn) ? csr[base + lane] : 0;
        int j = 0;
        for (; j + 8 <= nn; j += 8) {
            int s0 = __shfl_sync(0xffffffffu, s, j + 0 + half);
            int s1 = __shfl_sync(0xffffffffu, s, j + 2 + half);
            int s2 = __shfl_sync(0xffffffffu, s, j + 4 + half);
            int s3 = __shfl_sync(0xffffffffu, s, j + 6 + half);
            uint2 v0 = in2[(size_t)s0 * 16 + fl];
            uint2 v1 = in2[(size_t)s1 * 16 + fl];
            uint2 v2 = in2[(size_t)s2 * 16 + fl];
            uint2 v3 = in2[(size_t)s3 * 16 + fl];
            hacc(acc, v0); hacc(acc, v1); hacc(acc, v2); hacc(acc, v3);
        }
        for (; j + 2 <= nn; j += 2) {
            int s0 = __shfl_sync(0xffffffffu, s, j + half);
            uint2 v = in2[(size_t)s0 * 16 + fl];
            hacc(acc, v);
        }
        if (j < nn) {
            int s0 = __shfl_sync(0xffffffffu, s, j);
            if (half == 0) {
                uint2 v = in2[(size_t)s0 * 16 + fl];
                hacc(acc, v);
            }
        }
    }
    acc.x += __shfl_xor_sync(0xffffffffu, acc.x, 16);
    acc.y += __shfl_xor_sync(0xffffffffu, acc.y, 16);
    acc.z += __shfl_xor_sync(0xffffffffu, acc.z, 16);
    acc.w += __shfl_xor_sync(0xffffffffu, acc.w, 16);
    if (half == 0) {
        float iv = 1.0f / (float)max(end - start, 1);
        __half2 o0 = __floats2half2_rn(acc.x * iv, acc.y * iv);
        __half2 o1 = __floats2half2_rn(acc.z * iv, acc.w * iv);
        uint2 o;
        o.x = *(unsigned int*)&o0; o.y = *(unsigned int*)&o1;
        agg2[(size_t)wid * 16 + fl] = o;
    }
}

// ---------------- fp16 MMA helper (m16n8k16, fp32 accumulate) ----------------
__device__ __forceinline__ void mma_f16(float c[4], unsigned int a0, unsigned int a1,
                                        unsigned int a2, unsigned int a3,
                                        unsigned int b0, unsigned int b1) {
    asm volatile(
        "mma.sync.aligned.m16n8k16.row.col.f32.f16.f16.f32 "
        "{%0,%1,%2,%3}, {%4,%5,%6,%7}, {%8,%9}, {%0,%1,%2,%3};"
        : "+f"(c[0]), "+f"(c[1]), "+f"(c[2]), "+f"(c[3])
        : "r"(a0), "r"(a1), "r"(a2), "r"(a3), "r"(b0), "r"(b1));
}

// ---------------- fused SAGE layer GEMM (fp16 tensor core, 128-row tiles) ----------------
#define SA_W 68    // 64 k-words (agg 0..31 | h 32..63) + 4 pad; ≡4 mod 32
#define SX_W 36    // 32 k-words + 4
#define SW1_W 68
#define SW2_W 36
#define SMEM_WORDS (128*SA_W + 128*SX_W + 64*SW1_W + 64*SW2_W + 3*64)
#define SMEM_BYTES (SMEM_WORDS * 4)

__global__ void __launch_bounds__(256, 2)
sage_gemm_kernel(const __half* __restrict__ agg, const __half* __restrict__ h,
                 const __half* __restrict__ x,
                 const unsigned* __restrict__ w1h, const unsigned* __restrict__ w2h,
                 const float* __restrict__ bl, const float* __restrict__ bs,
                 const float* __restrict__ al,
                 float* __restrict__ outf, __half* __restrict__ outh,
                 int row_base, int nrows) {
    extern __shared__ unsigned int smu[];
    unsigned int* sA  = smu;                 // [128][SA_W]
    unsigned int* sX  = sA + 128 * SA_W;     // [128][SX_W]
    unsigned int* sW1 = sX + 128 * SX_W;     // [64 d][SW1_W]
    unsigned int* sW2 = sW1 + 64 * SW1_W;    // [64 d][SW2_W]
    float* sBL = (float*)(sW2 + 64 * SW2_W);
    float* sBS = sBL + 64;
    float* sAl = sBS + 64;

    int tid = threadIdx.x;
    int row0 = row_base + blockIdx.x * 128;

    for (int i = tid; i < 64 * 16; i += 256) {
        int d = i >> 4, q = i & 15;
        *(uint4*)(sW1 + d * SW1_W + q * 4) = ((const uint4*)w1h)[i];
    }
    for (int i = tid; i < 64 * 8; i += 256) {
        int d = i >> 3, q = i & 7;
        *(uint4*)(sW2 + d * SW2_W + q * 4) = ((const uint4*)w2h)[i];
    }
    if (tid < 64) { sBL[tid] = bl[tid]; sBS[tid] = bs[tid]; sAl[tid] = al[tid]; }

    bool hx = (h == x);
    for (int i = tid; i < 128 * 8; i += 256) {
        int r = i >> 3, c8 = i & 7;
        int row = row0 + r;
        uint4 pa = {0,0,0,0}, ph = pa, px = pa;
        if (row < nrows) {
            pa = ((const uint4*)agg)[(size_t)row * 8 + c8];
            px = ((const uint4*)x)[(size_t)row * 8 + c8];
            ph = hx ? px : ((const uint4*)h)[(size_t)row * 8 + c8];
        }
        *(uint4*)(sA + r * SA_W + c8 * 4)      = pa;
        *(uint4*)(sA + r * SA_W + 32 + c8 * 4) = ph;
        *(uint4*)(sX + r * SX_W + c8 * 4)      = px;
    }
    __syncthreads();

    int wid = tid >> 5, lane = tid & 31;
    int wy = wid >> 1, wx = wid & 1;
    int mrow = wy * 32;
    int ncol = wx * 32;
    int g = lane >> 2, tc = lane & 3;

    float acc[2][4][4];
#pragma unroll
    for (int mt = 0; mt < 2; mt++)
#pragma unroll
        for (int t = 0; t < 4; t++)
#pragma unroll
            for (int r = 0; r < 4; r++) acc[mt][t][r] = 0.f;

    // phase 1: agg@wl^T + h@wr^T  (K = 128 halves = 64 words, 8 k16-steps)
#pragma unroll
    for (int kk = 0; kk < 8; kk++) {
        int kw0 = kk * 8;
        unsigned int b0[4], b1[4];
#pragma unroll
        for (int t = 0; t < 4; t++) {
            int nb = ncol + t * 8;
            b0[t] = sW1[(nb + g) * SW1_W + kw0 + tc];
            b1[t] = sW1[(nb + g) * SW1_W + kw0 + tc + 4];
        }
#pragma unroll
        for (int mt = 0; mt < 2; mt++) {
            int rb = mrow + mt * 16;
            unsigned int a0 = sA[(rb + g) * SA_W + kw0 + tc];
            unsigned int a1 = sA[(rb + g + 8) * SA_W + kw0 + tc];
            unsigned int a2 = sA[(rb + g) * SA_W + kw0 + tc + 4];
            unsigned int a3 = sA[(rb + g + 8) * SA_W + kw0 + tc + 4];
#pragma unroll
            for (int t = 0; t < 4; t++)
                mma_f16(acc[mt][t], a0, a1, a2, a3, b0[t], b1[t]);
        }
    }

    // epilogue 1: bias + PReLU
#pragma unroll
    for (int mt = 0; mt < 2; mt++)
#pragma unroll
        for (int t = 0; t < 4; t++) {
            int col = ncol + t * 8 + tc * 2;
            float b0v = sBL[col], b1v = sBL[col + 1];
            float a0v = sAl[col], a1v = sAl[col + 1];
            float v;
            v = acc[mt][t][0] + b0v; acc[mt][t][0] = (v >= 0.f) ? v : a0v * v;
            v = acc[mt][t][1] + b1v; acc[mt][t][1] = (v >= 0.f) ? v : a1v * v;
            v = acc[mt][t][2] + b0v; acc[mt][t][2] = (v >= 0.f) ? v : a0v * v;
            v = acc[mt][t][3] + b1v; acc[mt][t][3] = (v >= 0.f) ? v : a1v * v;
        }

    // phase 2: += x@ws^T  (K = 64 halves = 32 words, 4 k16-steps)
#pragma unroll
    for (int kk = 0; kk < 4; kk++) {
        int kw0 = kk * 8;
        unsigned int b0[4], b1[4];
#pragma unroll
        for (int t = 0; t < 4; t++) {
            int nb = ncol + t * 8;
            b0[t] = sW2[(nb + g) * SW2_W + kw0 + tc];
            b1[t] = sW2[(nb + g) * SW2_W + kw0 + tc + 4];
        }
#pragma unroll
        for (int mt = 0; mt < 2; mt++) {
            int rb = mrow + mt * 16;
            unsigned int a0 = sX[(rb + g) * SX_W + kw0 + tc];
            unsigned int a1 = sX[(rb + g + 8) * SX_W + kw0 + tc];
            unsigned int a2 = sX[(rb + g) * SX_W + kw0 + tc + 4];
            unsigned int a3 = sX[(rb + g + 8) * SX_W + kw0 + tc + 4];
#pragma unroll
            for (int t = 0; t < 4; t++)
                mma_f16(acc[mt][t], a0, a1, a2, a3, b0[t], b1[t]);
        }
    }

    // epilogue 2: + bs, paired stores
#pragma unroll
    for (int mt = 0; mt < 2; mt++)
#pragma unroll
        for (int t = 0; t < 4; t++) {
            int col = ncol + t * 8 + tc * 2;
            float b0v = sBS[col], b1v = sBS[col + 1];
            int r0g = row0 + mrow + mt * 16 + g;
            int r1g = r0g + 8;
            if (outh) {
                if (r0g < nrows) {
                    __half2 o = __floats2half2_rn(acc[mt][t][0] + b0v, acc[mt][t][1] + b1v);
                    *(__half2*)(outh + (size_t)r0g * 64 + col) = o;
                }
                if (r1g < nrows) {
                    __half2 o = __floats2half2_rn(acc[mt][t][2] + b0v, acc[mt][t][3] + b1v);
                    *(__half2*)(outh + (size_t)r1g * 64 + col) = o;
                }
            } else {
                if (r0g < nrows) {
                    float2 o = {acc[mt][t][0] + b0v, acc[mt][t][1] + b1v};
                    *(float2*)(outf + (size_t)r0g * 64 + col) = o;
                }
                if (r1g < nrows) {
                    float2 o = {acc[mt][t][2] + b0v, acc[mt][t][3] + b1v};
                    *(float2*)(outf + (size_t)r1g * 64 + col) = o;
                }
            }
        }
}

// ---------------- launch ----------------
extern "C" void kernel_launch(void* const* d_in, const int* in_sizes, int n_in,
                              void* d_out, int out_size) {
    const float* x  = (const float*)d_in[0];
    const int*   ei = (const int*)d_in[1];    // int32 delivered (verified R1/R2)
    const float* wl0 = (const float*)d_in[2];
    const float* bl0 = (const float*)d_in[3];
    const float* wr0 = (const float*)d_in[4];
    const float* ws0 = (const float*)d_in[5];
    const float* bs0 = (const float*)d_in[6];
    const float* a0  = (const float*)d_in[7];
    const float* wl1 = (const float*)d_in[8];
    const float* bl1 = (const float*)d_in[9];
    const float* wr1 = (const float*)d_in[10];
    const float* ws1 = (const float*)d_in[11];
    const float* bs1 = (const float*)d_in[12];
    const float* a1  = (const float*)d_in[13];
    float* out = (float*)d_out;

    int N = in_sizes[0] / 64;
    int E = in_sizes[1] / 2;

    __half *xh, *h1, *agg;
    unsigned *w1h, *w2h;
    int *deg, *rp, *rank, *csr, *bsum;
    cudaGetSymbolAddress((void**)&xh,   g_xh);
    cudaGetSymbolAddress((void**)&h1,   g_h1);
    cudaGetSymbolAddress((void**)&agg,  g_agg);
    cudaGetSymbolAddress((void**)&w1h,  g_w1h);
    cudaGetSymbolAddress((void**)&w2h,  g_w2h);
    cudaGetSymbolAddress((void**)&deg,  g_deg);
    cudaGetSymbolAddress((void**)&rp,   g_rp);
    cudaGetSymbolAddress((void**)&rank, g_rank);
    cudaGetSymbolAddress((void**)&csr,  g_csr);
    cudaGetSymbolAddress((void**)&bsum, g_bsum);

    const int* src = ei;
    const int* dst = ei + E;

    // persistent side stream + events; created on the FIRST call (the
    // correctness run, not captured), reused identically every call.
    static cudaStream_t s2 = nullptr;
    static cudaEvent_t evFork, evXh, evL0, evFin, evG0[NCHUNK], evG1[NCHUNK];
    if (!s2) {
        cudaStreamCreateWithFlags(&s2, cudaStreamNonBlocking);
        cudaEventCreateWithFlags(&evFork, cudaEventDisableTiming);
        cudaEventCreateWithFlags(&evXh,   cudaEventDisableTiming);
        cudaEventCreateWithFlags(&evL0,   cudaEventDisableTiming);
        cudaEventCreateWithFlags(&evFin,  cudaEventDisableTiming);
        for (int c = 0; c < NCHUNK; c++) {
            cudaEventCreateWithFlags(&evG0[c], cudaEventDisableTiming);
            cudaEventCreateWithFlags(&evG1[c], cudaEventDisableTiming);
        }
    }

    cudaFuncSetAttribute(sage_gemm_kernel, cudaFuncAttributeMaxDynamicSharedMemorySize, SMEM_BYTES);

    // ---- fork s2 immediately: x->fp16 + weight prep ----
    cudaEventRecord(evFork, 0);
    cudaStreamWaitEvent(s2, evFork, 0);
    int n4 = N * DD / 8;
    f2h_kernel<<<(n4 + 255) / 256, 256, 0, s2>>>((const float4*)x, (uint4*)xh, n4);
    wprep_kernel<<<(2 * 64 * 32 + 255) / 256, 256, 0, s2>>>(wl0, wr0, ws0, wl1, wr1, ws1, w1h, w2h);
    cudaEventRecord(evXh, s2);

    // ---- s0: CSR build (rank-based, single atomic pass) ----
    cudaMemsetAsync(deg, 0, (size_t)N * sizeof(int), 0);
    int eq = (E + 3) / 4;
    degree_rank_kernel<<<(eq + 255) / 256, 256, 0, 0>>>(dst, deg, rank, E);
    int nb = (N + 1023) / 1024;
    scan1_kernel<<<nb, 256, 0, 0>>>(deg, rp, bsum, N);
    scan23_kernel<<<(N + 255) / 256, 256, 0, 0>>>(rp, bsum, nb, N);
    place_kernel<<<(eq + 255) / 256, 256, 0, 0>>>(src, dst, rank, rp, csr, E);

    // chunking (rows per chunk, multiple of 128)
    int base = (((N + NCHUNK - 1) / NCHUNK) + 127) & ~127;

    // ---- layer 0: gathers on s0 (need xh), gemms on s2 ----
    cudaStreamWaitEvent(0, evXh, 0);
    for (int c = 0; c < NCHUNK; c++) {
        int c0 = c * base;
        int cn = N - c0; if (cn <= 0) { cudaEventRecord(evG0[c], 0); continue; }
        if (cn > base) cn = base;
        int gb = (cn * 32 + 255) / 256;
        gather_kernel<<<gb, 256, 0, 0>>>((const uint2*)xh, rp, csr, (uint2*)agg, c0, c0 + cn);
        cudaEventRecord(evG0[c], 0);
    }
    for (int c = 0; c < NCHUNK; c++) {
        int c0 = c * base;
        int cn = N - c0; if (cn <= 0) continue;
        if (cn > base) cn = base;
        cudaStreamWaitEvent(s2, evG0[c], 0);
        int mb = (cn + 127) / 128;
        sage_gemm_kernel<<<mb, 256, SMEM_BYTES, s2>>>(
            agg, xh, xh, w1h, w2h, bl0, bs0, a0, nullptr, h1, c0, c0 + cn);
    }
    cudaEventRecord(evL0, s2);
    cudaStreamWaitEvent(0, evL0, 0);

    // ---- layer 1: gathers on s0 (need full h1), gemms on s2 ----
    for (int c = 0; c < NCHUNK; c++) {
        int c0 = c * base;
        int cn = N - c0; if (cn <= 0) { cudaEventRecord(evG1[c], 0); continue; }
        if (cn > base) cn = base;
        int gb = (cn * 32 + 255) / 256;
        gather_kernel<<<gb, 256, 0, 0>>>((const uint2*)h1, rp, csr, (uint2*)agg, c0, c0 + cn);
        cudaEventRecord(evG1[c], 0);
    }
    for (int c = 0; c < NCHUNK; c++) {
        int c0 = c * base;
        int cn = N - c0; if (cn <= 0) continue;
        if (cn > base) cn = base;
        cudaStreamWaitEvent(s2, evG1[c], 0);
        int mb = (cn + 127) / 128;
        sage_gemm_kernel<<<mb, 256, SMEM_BYTES, s2>>>(
            agg, h1, xh, w1h + 4096, w2h + 2048, bl1, bs1, a1, out, nullptr, c0, c0 + cn);
    }
    cudaEventRecord(evFin, s2);
    cudaStreamWaitEvent(0, evFin, 0);
}

// round 16
// speedup vs baseline: 1.2069x; 1.2069x over previous
#include <cuda_runtime.h>
#include <cuda_fp16.h>
#include <cstdint>

#define NN 100000
#define DD 64
#define EE 1600000
#define NCHUNK 4

// ---------------- scratch (no allocs allowed) ----------------
__device__ __align__(16) __half g_xh[NN * DD];   // fp16 copy of x
__device__ __align__(16) __half g_h1[NN * DD];   // fp16 layer-0 output
__device__ __align__(16) __half g_agg[NN * DD];  // fp16 aggregated neighbors
__device__ __align__(16) unsigned g_w1h[2 * 64 * 64];  // fp16 [wl|wr] per layer, [d][kw]
__device__ __align__(16) unsigned g_w2h[2 * 64 * 32];  // fp16 ws per layer
__device__ int g_deg[NN];
__device__ int g_rp[NN + 1];
__device__ __align__(16) int g_rank[EE];   // intra-bucket rank per edge
__device__ int g_csr[EE];
__device__ int g_bsum[128];

// ---------------- degree + rank over dst half, 4 edges/thread ----------------
__global__ void degree_rank_kernel(const int* __restrict__ dst, int* __restrict__ deg,
                                   int* __restrict__ rank, int E) {
    int i = blockIdx.x * blockDim.x + threadIdx.x;
    int e = i * 4;
    if (e + 3 < E) {
        int4 d = ((const int4*)dst)[i];
        int4 r;
        r.x = atomicAdd(&deg[d.x], 1);
        r.y = atomicAdd(&deg[d.y], 1);
        r.z = atomicAdd(&deg[d.z], 1);
        r.w = atomicAdd(&deg[d.w], 1);
        ((int4*)rank)[i] = r;
    } else if (e < E) {
        for (int j = e; j < E; j++) rank[j] = atomicAdd(&deg[dst[j]], 1);
    }
}

// ---------------- fp32 -> fp16 row conversion ----------------
__global__ void f2h_kernel(const float4* __restrict__ in, uint4* __restrict__ out, int n4) {
    int i = blockIdx.x * blockDim.x + threadIdx.x;
    if (i >= n4) return;
    float4 a = in[2 * i], b = in[2 * i + 1];
    __half2 h0 = __floats2half2_rn(a.x, a.y);
    __half2 h1 = __floats2half2_rn(a.z, a.w);
    __half2 h2 = __floats2half2_rn(b.x, b.y);
    __half2 h3 = __floats2half2_rn(b.z, b.w);
    uint4 o;
    o.x = *(unsigned int*)&h0; o.y = *(unsigned int*)&h1;
    o.z = *(unsigned int*)&h2; o.w = *(unsigned int*)&h3;
    out[i] = o;
}

// ---------------- weight precompute: fp32 -> fp16 packed, both layers ----------------
__global__ void wprep_kernel(const float* __restrict__ wl0, const float* __restrict__ wr0,
                             const float* __restrict__ ws0,
                             const float* __restrict__ wl1, const float* __restrict__ wr1,
                             const float* __restrict__ ws1,
                             unsigned* __restrict__ w1h, unsigned* __restrict__ w2h) {
    int i = blockIdx.x * blockDim.x + threadIdx.x;
    if (i >= 2 * 64 * 32) return;
    int L = i >> 11, r = i & 2047;
    int d = r >> 5, kw = r & 31;
    const float* wl = L ? wl1 : wl0;
    const float* wr = L ? wr1 : wr0;
    const float* ws = L ? ws1 : ws0;
    float2 vl = ((const float2*)wl)[d * 32 + kw];
    float2 vr = ((const float2*)wr)[d * 32 + kw];
    float2 vs = ((const float2*)ws)[d * 32 + kw];
    __half2 hl = __floats2half2_rn(vl.x, vl.y);
    __half2 hr = __floats2half2_rn(vr.x, vr.y);
    __half2 hs = __floats2half2_rn(vs.x, vs.y);
    w1h[L * 4096 + d * 64 + kw]      = *(unsigned int*)&hl;
    w1h[L * 4096 + d * 64 + 32 + kw] = *(unsigned int*)&hr;
    w2h[L * 2048 + d * 32 + kw]      = *(unsigned int*)&hs;
}

// ---------------- scan pass 1 (per-1024 block partials) ----------------
__global__ void scan1_kernel(const int* __restrict__ deg, int* __restrict__ rp,
                             int* __restrict__ bsum, int n) {
    __shared__ int wsum[8];
    int t = threadIdx.x;
    int base = blockIdx.x * 1024 + t * 4;
    int v[4];
#pragma unroll
    for (int j = 0; j < 4; j++) v[j] = (base + j < n) ? deg[base + j] : 0;
    int tot = v[0] + v[1] + v[2] + v[3];
    int lane = t & 31, w = t >> 5;
    int inc = tot;
#pragma unroll
    for (int d = 1; d < 32; d <<= 1) {
        int o = __shfl_up_sync(0xffffffffu, inc, d);
        if (lane >= d) inc += o;
    }
    if (lane == 31) wsum[w] = inc;
    __syncthreads();
    if (t == 0) {
        int r = 0;
#pragma unroll
        for (int i = 0; i < 8; i++) { int x = wsum[i]; wsum[i] = r; r += x; }
    }
    __syncthreads();
    int excl = wsum[w] + inc - tot;
    int r = excl;
#pragma unroll
    for (int j = 0; j < 4; j++) {
        if (base + j < n) rp[base + j] = r;
        r += v[j];
    }
    if (t == 255) bsum[blockIdx.x] = wsum[7] + inc;
}

// ---------------- scan pass 2+3 fused: add block prefixes ----------------
__global__ void scan23_kernel(int* __restrict__ rp, const int* __restrict__ bsum,
                              int nb, int n) {
    __shared__ int pref[129];
    int t = threadIdx.x;
    if (t < 32) {
        int carry = 0;
        for (int base = 0; base < nb; base += 32) {
            int v = (base + t < nb) ? bsum[base + t] : 0;
            int inc = v;
#pragma unroll
            for (int d = 1; d < 32; d <<= 1) {
                int o = __shfl_up_sync(0xffffffffu, inc, d);
                if (t >= d) inc += o;
            }
            if (base + t < nb) pref[base + t] = carry + inc - v;
            carry += __shfl_sync(0xffffffffu, inc, 31);
        }
        if (t == 0) pref[128] = carry;
    }
    __syncthreads();
    int i = blockIdx.x * blockDim.x + t;
    if (i < n) rp[i] += pref[i >> 10];
    if (blockIdx.x == 0 && t == 0) rp[n] = pref[128];
}

// ---------------- CSR placement: atomic-free streaming pass ----------------
__global__ void place_kernel(const int* __restrict__ src, const int* __restrict__ dst,
                             const int* __restrict__ rank, const int* __restrict__ rp,
                             int* __restrict__ csr, int E) {
    int i = blockIdx.x * blockDim.x + threadIdx.x;
    int e = i * 4;
    if (e + 3 < E) {
        int4 s = ((const int4*)src)[i];
        int4 d = ((const int4*)dst)[i];
        int4 r = ((const int4*)rank)[i];
        csr[rp[d.x] + r.x] = s.x;
        csr[rp[d.y] + r.y] = s.y;
        csr[rp[d.z] + r.z] = s.z;
        csr[rp[d.w] + r.w] = s.w;
    } else if (e < E) {
        for (int j = e; j < E; j++)
            csr[rp[dst[j]] + rank[j]] = src[j];
    }
}

// ---------------- CSR mean-gather: warp/node, half-warp/neighbor, fp16 rows ----------------
__device__ __forceinline__ void hacc(float4& a, uint2 v) {
    float2 f0 = __half22float2(*(__half2*)&v.x);
    float2 f1 = __half22float2(*(__half2*)&v.y);
    a.x += f0.x; a.y += f0.y; a.z += f1.x; a.w += f1.y;
}

__global__ void __launch_bounds__(256)
gather_kernel(const uint2* __restrict__ in2, const int* __restrict__ rp,
              const int* __restrict__ csr, uint2* __restrict__ agg2,
              int wid0, int wid1) {
    int wid = wid0 + ((blockIdx.x * blockDim.x + threadIdx.x) >> 5);
    if (wid >= wid1) return;
    int lane = threadIdx.x & 31;
    int half = lane >> 4;
    int fl = lane & 15;
    int start = rp[wid], end = rp[wid + 1];
    float4 acc = {0.f, 0.f, 0.f, 0.f};
    for (int base = start; base < end; base += 32) {
        int nn = min(32, end - base);
        int s = (lane < nn) ? csr[base + lane] : 0;
        int j = 0;
        for (; j + 8 <= nn; j += 8) {
            int s0 = __shfl_sync(0xffffffffu, s, j + 0 + half);
            int s1 = __shfl_sync(0xffffffffu, s, j + 2 + half);
            int s2 = __shfl_sync(0xffffffffu, s, j + 4 + half);
            int s3 = __shfl_sync(0xffffffffu, s, j + 6 + half);
            uint2 v0 = in2[(size_t)s0 * 16 + fl];
            uint2 v1 = in2[(size_t)s1 * 16 + fl];
            uint2 v2 = in2[(size_t)s2 * 16 + fl];
            uint2 v3 = in2[(size_t)s3 * 16 + fl];
            hacc(acc, v0); hacc(acc, v1); hacc(acc, v2); hacc(acc, v3);
        }
        for (; j + 2 <= nn; j += 2) {
            int s0 = __shfl_sync(0xffffffffu, s, j + half);
            uint2 v = in2[(size_t)s0 * 16 + fl];
            hacc(acc, v);
        }
        if (j < nn) {
            int s0 = __shfl_sync(0xffffffffu, s, j);
            if (half == 0) {
                uint2 v = in2[(size_t)s0 * 16 + fl];
                hacc(acc, v);
            }
        }
    }
    acc.x += __shfl_xor_sync(0xffffffffu, acc.x, 16);
    acc.y += __shfl_xor_sync(0xffffffffu, acc.y, 16);
    acc.z += __shfl_xor_sync(0xffffffffu, acc.z, 16);
    acc.w += __shfl_xor_sync(0xffffffffu, acc.w, 16);
    if (half == 0) {
        float iv = 1.0f / (float)max(end - start, 1);
        __half2 o0 = __floats2half2_rn(acc.x * iv, acc.y * iv);
        __half2 o1 = __floats2half2_rn(acc.z * iv, acc.w * iv);
        uint2 o;
        o.x = *(unsigned int*)&o0; o.y = *(unsigned int*)&o1;
        agg2[(size_t)wid * 16 + fl] = o;
    }
}

// ---------------- fp16 MMA helper (m16n8k16, fp32 accumulate) ----------------
__device__ __forceinline__ void mma_f16(float c[4], unsigned int a0, unsigned int a1,
                                        unsigned int a2, unsigned int a3,
                                        unsigned int b0, unsigned int b1) {
    asm volatile(
        "mma.sync.aligned.m16n8k16.row.col.f32.f16.f16.f32 "
        "{%0,%1,%2,%3}, {%4,%5,%6,%7}, {%8,%9}, {%0,%1,%2,%3};"
        : "+f"(c[0]), "+f"(c[1]), "+f"(c[2]), "+f"(c[3])
        : "r"(a0), "r"(a1), "r"(a2), "r"(a3), "r"(b0), "r"(b1));
}

// ---------------- fused SAGE layer GEMM (fp16 tensor core, 128-row tiles) ----------------
#define SA_W 68    // 64 k-words (agg 0..31 | h 32..63) + 4 pad; ≡4 mod 32
#define SX_W 36    // 32 k-words + 4
#define SW1_W 68
#define SW2_W 36
#define SMEM_WORDS (128*SA_W + 128*SX_W + 64*SW1_W + 64*SW2_W + 3*64)
#define SMEM_BYTES (SMEM_WORDS * 4)

__global__ void __launch_bounds__(256, 2)
sage_gemm_kernel(const __half* __restrict__ agg, const __half* __restrict__ h,
                 const __half* __restrict__ x,
                 const unsigned* __restrict__ w1h, const unsigned* __restrict__ w2h,
                 const float* __restrict__ bl, const float* __restrict__ bs,
                 const float* __restrict__ al,
                 float* __restrict__ outf, __half* __restrict__ outh,
                 int row_base, int nrows) {
    extern __shared__ unsigned int smu[];
    unsigned int* sA  = smu;                 // [128][SA_W]
    unsigned int* sX  = sA + 128 * SA_W;     // [128][SX_W]
    unsigned int* sW1 = sX + 128 * SX_W;     // [64 d][SW1_W]
    unsigned int* sW2 = sW1 + 64 * SW1_W;    // [64 d][SW2_W]
    float* sBL = (float*)(sW2 + 64 * SW2_W);
    float* sBS = sBL + 64;
    float* sAl = sBS + 64;

    int tid = threadIdx.x;
    int row0 = row_base + blockIdx.x * 128;

    for (int i = tid; i < 64 * 16; i += 256) {
        int d = i >> 4, q = i & 15;
        *(uint4*)(sW1 + d * SW1_W + q * 4) = ((const uint4*)w1h)[i];
    }
    for (int i = tid; i < 64 * 8; i += 256) {
        int d = i >> 3, q = i & 7;
        *(uint4*)(sW2 + d * SW2_W + q * 4) = ((const uint4*)w2h)[i];
    }
    if (tid < 64) { sBL[tid] = bl[tid]; sBS[tid] = bs[tid]; sAl[tid] = al[tid]; }

    bool hx = (h == x);
    for (int i = tid; i < 128 * 8; i += 256) {
        int r = i >> 3, c8 = i & 7;
        int row = row0 + r;
        uint4 pa = {0,0,0,0}, ph = pa, px = pa;
        if (row < nrows) {
            pa = ((const uint4*)agg)[(size_t)row * 8 + c8];
            px = ((const uint4*)x)[(size_t)row * 8 + c8];
            ph = hx ? px : ((const uint4*)h)[(size_t)row * 8 + c8];
        }
        *(uint4*)(sA + r * SA_W + c8 * 4)      = pa;
        *(uint4*)(sA + r * SA_W + 32 + c8 * 4) = ph;
        *(uint4*)(sX + r * SX_W + c8 * 4)      = px;
    }
    __syncthreads();

    int wid = tid >> 5, lane = tid & 31;
    int wy = wid >> 1, wx = wid & 1;
    int mrow = wy * 32;
    int ncol = wx * 32;
    int g = lane >> 2, tc = lane & 3;

    float acc[2][4][4];
#pragma unroll
    for (int mt = 0; mt < 2; mt++)
#pragma unroll
        for (int t = 0; t < 4; t++)
#pragma unroll
            for (int r = 0; r < 4; r++) acc[mt][t][r] = 0.f;

    // phase 1: agg@wl^T + h@wr^T  (K = 128 halves = 64 words, 8 k16-steps)
#pragma unroll
    for (int kk = 0; kk < 8; kk++) {
        int kw0 = kk * 8;
        unsigned int b0[4], b1[4];
#pragma unroll
        for (int t = 0; t < 4; t++) {
            int nb = ncol + t * 8;
            b0[t] = sW1[(nb + g) * SW1_W + kw0 + tc];
            b1[t] = sW1[(nb + g) * SW1_W + kw0 + tc + 4];
        }
#pragma unroll
        for (int mt = 0; mt < 2; mt++) {
            int rb = mrow + mt * 16;
            unsigned int a0 = sA[(rb + g) * SA_W + kw0 + tc];
            unsigned int a1 = sA[(rb + g + 8) * SA_W + kw0 + tc];
            unsigned int a2 = sA[(rb + g) * SA_W + kw0 + tc + 4];
            unsigned int a3 = sA[(rb + g + 8) * SA_W + kw0 + tc + 4];
#pragma unroll
            for (int t = 0; t < 4; t++)
                mma_f16(acc[mt][t], a0, a1, a2, a3, b0[t], b1[t]);
        }
    }

    // epilogue 1: bias + PReLU
#pragma unroll
    for (int mt = 0; mt < 2; mt++)
#pragma unroll
        for (int t = 0; t < 4; t++) {
            int col = ncol + t * 8 + tc * 2;
            float b0v = sBL[col], b1v = sBL[col + 1];
            float a0v = sAl[col], a1v = sAl[col + 1];
            float v;
            v = acc[mt][t][0] + b0v; acc[mt][t][0] = (v >= 0.f) ? v : a0v * v;
            v = acc[mt][t][1] + b1v; acc[mt][t][1] = (v >= 0.f) ? v : a1v * v;
            v = acc[mt][t][2] + b0v; acc[mt][t][2] = (v >= 0.f) ? v : a0v * v;
            v = acc[mt][t][3] + b1v; acc[mt][t][3] = (v >= 0.f) ? v : a1v * v;
        }

    // phase 2: += x@ws^T  (K = 64 halves = 32 words, 4 k16-steps)
#pragma unroll
    for (int kk = 0; kk < 4; kk++) {
        int kw0 = kk * 8;
        unsigned int b0[4], b1[4];
#pragma unroll
        for (int t = 0; t < 4; t++) {
            int nb = ncol + t * 8;
            b0[t] = sW2[(nb + g) * SW2_W + kw0 + tc];
            b1[t] = sW2[(nb + g) * SW2_W + kw0 + tc + 4];
        }
#pragma unroll
        for (int mt = 0; mt < 2; mt++) {
            int rb = mrow + mt * 16;
            unsigned int a0 = sX[(rb + g) * SX_W + kw0 + tc];
            unsigned int a1 = sX[(rb + g + 8) * SX_W + kw0 + tc];
            unsigned int a2 = sX[(rb + g) * SX_W + kw0 + tc + 4];
            unsigned int a3 = sX[(rb + g + 8) * SX_W + kw0 + tc + 4];
#pragma unroll
            for (int t = 0; t < 4; t++)
                mma_f16(acc[mt][t], a0, a1, a2, a3, b0[t], b1[t]);
        }
    }

    // epilogue 2: + bs, paired stores
#pragma unroll
    for (int mt = 0; mt < 2; mt++)
#pragma unroll
        for (int t = 0; t < 4; t++) {
            int col = ncol + t * 8 + tc * 2;
            float b0v = sBS[col], b1v = sBS[col + 1];
            int r0g = row0 + mrow + mt * 16 + g;
            int r1g = r0g + 8;
            if (outh) {
                if (r0g < nrows) {
                    __half2 o = __floats2half2_rn(acc[mt][t][0] + b0v, acc[mt][t][1] + b1v);
                    *(__half2*)(outh + (size_t)r0g * 64 + col) = o;
                }
                if (r1g < nrows) {
                    __half2 o = __floats2half2_rn(acc[mt][t][2] + b0v, acc[mt][t][3] + b1v);
                    *(__half2*)(outh + (size_t)r1g * 64 + col) = o;
                }
            } else {
                if (r0g < nrows) {
                    float2 o = {acc[mt][t][0] + b0v, acc[mt][t][1] + b1v};
                    *(float2*)(outf + (size_t)r0g * 64 + col) = o;
                }
                if (r1g < nrows) {
                    float2 o = {acc[mt][t][2] + b0v, acc[mt][t][3] + b1v};
                    *(float2*)(outf + (size_t)r1g * 64 + col) = o;
                }
            }
        }
}

// ---------------- launch ----------------
extern "C" void kernel_launch(void* const* d_in, const int* in_sizes, int n_in,
                              void* d_out, int out_size) {
    const float* x  = (const float*)d_in[0];
    const int*   ei = (const int*)d_in[1];    // int32 delivered (verified R1/R2)
    const float* wl0 = (const float*)d_in[2];
    const float* bl0 = (const float*)d_in[3];
    const float* wr0 = (const float*)d_in[4];
    const float* ws0 = (const float*)d_in[5];
    const float* bs0 = (const float*)d_in[6];
    const float* a0  = (const float*)d_in[7];
    const float* wl1 = (const float*)d_in[8];
    const float* bl1 = (const float*)d_in[9];
    const float* wr1 = (const float*)d_in[10];
    const float* ws1 = (const float*)d_in[11];
    const float* bs1 = (const float*)d_in[12];
    const float* a1  = (const float*)d_in[13];
    float* out = (float*)d_out;

    int N = in_sizes[0] / 64;
    int E = in_sizes[1] / 2;

    __half *xh, *h1, *agg;
    unsigned *w1h, *w2h;
    int *deg, *rp, *rank, *csr, *bsum;
    cudaGetSymbolAddress((void**)&xh,   g_xh);
    cudaGetSymbolAddress((void**)&h1,   g_h1);
    cudaGetSymbolAddress((void**)&agg,  g_agg);
    cudaGetSymbolAddress((void**)&w1h,  g_w1h);
    cudaGetSymbolAddress((void**)&w2h,  g_w2h);
    cudaGetSymbolAddress((void**)&deg,  g_deg);
    cudaGetSymbolAddress((void**)&rp,   g_rp);
    cudaGetSymbolAddress((void**)&rank, g_rank);
    cudaGetSymbolAddress((void**)&csr,  g_csr);
    cudaGetSymbolAddress((void**)&bsum, g_bsum);

    const int* src = ei;
    const int* dst = ei + E;

    // persistent side stream + events; created on the FIRST call (the
    // correctness run, not captured), reused identically every call.
    static cudaStream_t s2 = nullptr;
    static cudaEvent_t evFork, evXh, evL0, evFin, evG0[NCHUNK], evG1[NCHUNK];
    if (!s2) {
        cudaStreamCreateWithFlags(&s2, cudaStreamNonBlocking);
        cudaEventCreateWithFlags(&evFork, cudaEventDisableTiming);
        cudaEventCreateWithFlags(&evXh,   cudaEventDisableTiming);
        cudaEventCreateWithFlags(&evL0,   cudaEventDisableTiming);
        cudaEventCreateWithFlags(&evFin,  cudaEventDisableTiming);
        for (int c = 0; c < NCHUNK; c++) {
            cudaEventCreateWithFlags(&evG0[c], cudaEventDisableTiming);
            cudaEventCreateWithFlags(&evG1[c], cudaEventDisableTiming);
        }
    }

    cudaFuncSetAttribute(sage_gemm_kernel, cudaFuncAttributeMaxDynamicSharedMemorySize, SMEM_BYTES);

    // ---- fork s2 immediately: x->fp16 + weight prep ----
    cudaEventRecord(evFork, 0);
    cudaStreamWaitEvent(s2, evFork, 0);
    int n4 = N * DD / 8;
    f2h_kernel<<<(n4 + 255) / 256, 256, 0, s2>>>((const float4*)x, (uint4*)xh, n4);
    wprep_kernel<<<(2 * 64 * 32 + 255) / 256, 256, 0, s2>>>(wl0, wr0, ws0, wl1, wr1, ws1, w1h, w2h);
    cudaEventRecord(evXh, s2);

    // ---- s0: CSR build (rank-based, single atomic pass) ----
    cudaMemsetAsync(deg, 0, (size_t)N * sizeof(int), 0);
    int eq = (E + 3) / 4;
    degree_rank_kernel<<<(eq + 255) / 256, 256, 0, 0>>>(dst, deg, rank, E);
    int nb = (N + 1023) / 1024;
    scan1_kernel<<<nb, 256, 0, 0>>>(deg, rp, bsum, N);
    scan23_kernel<<<(N + 255) / 256, 256, 0, 0>>>(rp, bsum, nb, N);
    place_kernel<<<(eq + 255) / 256, 256, 0, 0>>>(src, dst, rank, rp, csr, E);

    // chunking (rows per chunk, multiple of 128)
    int base = (((N + NCHUNK - 1) / NCHUNK) + 127) & ~127;

    // ---- layer 0: gathers on s0 (need xh), gemms on s2 ----
    cudaStreamWaitEvent(0, evXh, 0);
    for (int c = 0; c < NCHUNK; c++) {
        int c0 = c * base;
        int cn = N - c0; if (cn <= 0) { cudaEventRecord(evG0[c], 0); continue; }
        if (cn > base) cn = base;
        int gb = (cn * 32 + 255) / 256;
        gather_kernel<<<gb, 256, 0, 0>>>((const uint2*)xh, rp, csr, (uint2*)agg, c0, c0 + cn);
        cudaEventRecord(evG0[c], 0);
    }
    for (int c = 0; c < NCHUNK; c++) {
        int c0 = c * base;
        int cn = N - c0; if (cn <= 0) continue;
        if (cn > base) cn = base;
        cudaStreamWaitEvent(s2, evG0[c], 0);
        int mb = (cn + 127) / 128;
        sage_gemm_kernel<<<mb, 256, SMEM_BYTES, s2>>>(
            agg, xh, xh, w1h, w2h, bl0, bs0, a0, nullptr, h1, c0, c0 + cn);
    }
    cudaEventRecord(evL0, s2);
    cudaStreamWaitEvent(0, evL0, 0);

    // ---- layer 1: gathers on s0 (need full h1), gemms on s2 ----
    for (int c = 0; c < NCHUNK; c++) {
        int c0 = c * base;
        int cn = N - c0; if (cn <= 0) { cudaEventRecord(evG1[c], 0); continue; }
        if (cn > base) cn = base;
        int gb = (cn * 32 + 255) / 256;
        gather_kernel<<<gb, 256, 0, 0>>>((const uint2*)h1, rp, csr, (uint2*)agg, c0, c0 + cn);
        cudaEventRecord(evG1[c], 0);
    }
    for (int c = 0; c < NCHUNK; c++) {
        int c0 = c * base;
        int cn = N - c0; if (cn <= 0) continue;
        if (cn > base) cn = base;
        cudaStreamWaitEvent(s2, evG1[c], 0);
        int mb = (cn + 127) / 128;
        sage_gemm_kernel<<<mb, 256, SMEM_BYTES, s2>>>(
            agg, h1, xh, w1h + 4096, w2h + 2048, bl1, bs1, a1, out, nullptr, c0, c0 + cn);
    }
    cudaEventRecord(evFin, s2);
    cudaStreamWaitEvent(0, evFin, 0);
}